// round 2
// baseline (speedup 1.0000x reference)
#include <cuda_runtime.h>
#include <cstdint>

// ---------------------------------------------------------------------------
// GeometricPositionalFingerprinter — Round 2
// Input : pentachora [V, 5, 128] f32  (V = in_sizes[0]/640)
// Output: cantor fingerprint [V] f32
//
// Layout: 4 lanes per pentachoron (8 pentachora per warp), float4 columns.
// R2 changes vs R1 (numerics bit-identical — only LOAD timing moved):
//   * explicit double-buffer prefetch of the next chunk's 5 float4 loads
//   * __ldcs evict-streaming loads (data read exactly once)
// Accumulation order per accumulator is unchanged; rel_err must reproduce.
// ---------------------------------------------------------------------------

__device__ __forceinline__ float sigmoid_pos(float x) {
    // x >= 0 always. ~2 ulp regardless of fast-math flags.
    if (x > 18.0f) return 1.0f;
    float t = -x;
    float kf = rintf(t * 1.4426950408889634f);
    float r = fmaf(-kf, 0.693145751953125f, t);
    r = fmaf(-kf, 1.428606765330187e-06f, r);
    float p = fmaf(r, 1.38888889e-3f, 8.33333333e-3f);
    p = fmaf(r, p, 4.16666667e-2f);
    p = fmaf(r, p, 1.66666667e-1f);
    p = fmaf(r, p, 0.5f);
    p = fmaf(r, p, 1.0f);
    p = fmaf(r, p, 1.0f);
    int ki = (int)kf;
    float scale = __int_as_float((ki + 127) << 23);
    float e = p * scale;
    return __fdiv_rn(1.0f, __fadd_rn(1.0f, e));
}

__global__ void __launch_bounds__(256)
gpf_kernel(const float* __restrict__ pent, float* __restrict__ out, int V)
{
    int tid = blockIdx.x * 256 + threadIdx.x;
    int g = tid >> 2;        // pentachoron index
    int s = tid & 3;         // sublane within 4-lane group
    if (g >= V) return;

    const float4* __restrict__ base =
        reinterpret_cast<const float4*>(pent) + (size_t)g * 160 + s;

    float acc[15];  // gram upper triangle incl diagonal (i<=j)
    float cd[5];    // squared distance to centroid per vertex
#pragma unroll
    for (int i = 0; i < 15; ++i) acc[i] = 0.0f;
#pragma unroll
    for (int v = 0; v < 5; ++v) cd[v] = 0.0f;

    // Prime the pipeline: chunk 0 loads.
    float4 cur[5];
#pragma unroll
    for (int v = 0; v < 5; ++v) cur[v] = __ldcs(base + v * 32);

#pragma unroll
    for (int c = 0; c < 8; ++c) {
        // Prefetch chunk c+1 BEFORE computing chunk c (load timing only;
        // per-accumulator FMA order identical to R1).
        float4 nxt[5];
        if (c < 7) {
#pragma unroll
            for (int v = 0; v < 5; ++v)
                nxt[v] = __ldcs(base + v * 32 + (c + 1) * 4);
        }

        float4 a0 = cur[0], a1 = cur[1], a2 = cur[2], a3 = cur[3], a4 = cur[4];

        float cx = (((a0.x + a1.x) + (a2.x + a3.x)) + a4.x) * 0.2f;
        float cy = (((a0.y + a1.y) + (a2.y + a3.y)) + a4.y) * 0.2f;
        float cz = (((a0.z + a1.z) + (a2.z + a3.z)) + a4.z) * 0.2f;
        float cw = (((a0.w + a1.w) + (a2.w + a3.w)) + a4.w) * 0.2f;

        {
            const float4 aa[5] = {a0, a1, a2, a3, a4};
            int k = 0;
#pragma unroll
            for (int i = 0; i < 5; ++i) {
#pragma unroll
                for (int j = i; j < 5; ++j) {
                    float t = acc[k];
                    t = fmaf(aa[i].x, aa[j].x, t);
                    t = fmaf(aa[i].y, aa[j].y, t);
                    t = fmaf(aa[i].z, aa[j].z, t);
                    t = fmaf(aa[i].w, aa[j].w, t);
                    acc[k] = t;
                    ++k;
                }
            }
#pragma unroll
            for (int v = 0; v < 5; ++v) {
                float dx = aa[v].x - cx;
                float dy = aa[v].y - cy;
                float dz = aa[v].z - cz;
                float dw = aa[v].w - cw;
                float t = cd[v];
                t = fmaf(dx, dx, t);
                t = fmaf(dy, dy, t);
                t = fmaf(dz, dz, t);
                t = fmaf(dw, dw, t);
                cd[v] = t;
            }
        }

        if (c < 7) {
#pragma unroll
            for (int v = 0; v < 5; ++v) cur[v] = nxt[v];
        }
    }

    // Butterfly reduce across the 4-lane group (same tree as R1).
#pragma unroll
    for (int i = 0; i < 15; ++i) {
        acc[i] += __shfl_xor_sync(0xffffffffu, acc[i], 1);
        acc[i] += __shfl_xor_sync(0xffffffffu, acc[i], 2);
    }
#pragma unroll
    for (int v = 0; v < 5; ++v) {
        cd[v] += __shfl_xor_sync(0xffffffffu, cd[v], 1);
        cd[v] += __shfl_xor_sync(0xffffffffu, cd[v], 2);
    }

    // Unpack full symmetric gram
    float gm[5][5];
    {
        int k = 0;
#pragma unroll
        for (int i = 0; i < 5; ++i)
#pragma unroll
            for (int j = i; j < 5; ++j) {
                gm[i][j] = acc[k];
                gm[j][i] = acc[k];
                ++k;
            }
    }

    // --- Edge statistics (triu order = np.triu_indices(5, k=1)) ---
    float e[10];
    {
        int m = 0;
#pragma unroll
        for (int i = 0; i < 5; ++i)
#pragma unroll
            for (int j = i + 1; j < 5; ++j) {
                float ds = __fsub_rn(__fadd_rn(gm[i][i], gm[j][j]),
                                     __fmul_rn(2.0f, gm[i][j]));
                ds = fmaxf(ds, 0.0f);
                e[m++] = __fsqrt_rn(ds);
            }
    }
    float esum = 0.0f;
#pragma unroll
    for (int i = 0; i < 10; ++i) esum = __fadd_rn(esum, e[i]);
    float mean_edge = __fdiv_rn(esum, 10.0f);
    float ess = 0.0f;
#pragma unroll
    for (int i = 0; i < 10; ++i) {
        float d = __fsub_rn(e[i], mean_edge);
        ess = fmaf(d, d, ess);
    }
    float std_edge = __fsqrt_rn(__fdiv_rn(ess, 9.0f));
    float ratio = __fdiv_rn(std_edge, __fadd_rn(mean_edge, 1e-6f));

    // --- Vertex spread (ddof=1) ---
    float dc[5];
    float csum = 0.0f;
#pragma unroll
    for (int v = 0; v < 5; ++v) {
        dc[v] = __fsqrt_rn(cd[v]);
        csum = __fadd_rn(csum, dc[v]);
    }
    float cmean = __fdiv_rn(csum, 5.0f);
    float css = 0.0f;
#pragma unroll
    for (int v = 0; v < 5; ++v) {
        float d = __fsub_rn(dc[v], cmean);
        css = fmaf(d, d, css);
    }
    float spread = __fsqrt_rn(__fdiv_rn(css, 4.0f));

    // --- Volume via 4x4 edge-vector Gram det (saturated sigmoid -> 1.0f) ---
    float G[4][4];
#pragma unroll
    for (int i = 0; i < 4; ++i)
#pragma unroll
        for (int j = 0; j < 4; ++j)
            G[i][j] = (gm[i + 1][j + 1] - gm[0][i + 1]) - (gm[0][j + 1] - gm[0][0]);

    float d2233 = G[2][2] * G[3][3] - G[2][3] * G[3][2];
    float d2133 = G[2][1] * G[3][3] - G[2][3] * G[3][1];
    float d2132 = G[2][1] * G[3][2] - G[2][2] * G[3][1];
    float d2033 = G[2][0] * G[3][3] - G[2][3] * G[3][0];
    float d2032 = G[2][0] * G[3][2] - G[2][2] * G[3][0];
    float d2031 = G[2][0] * G[3][1] - G[2][1] * G[3][0];
    float c0 = G[1][1] * d2233 - G[1][2] * d2133 + G[1][3] * d2132;
    float c1 = G[1][0] * d2233 - G[1][2] * d2033 + G[1][3] * d2032;
    float c2 = G[1][0] * d2133 - G[1][1] * d2033 + G[1][3] * d2031;
    float c3 = G[1][0] * d2132 - G[1][1] * d2032 + G[1][2] * d2031;
    float det = G[0][0] * c0 - G[0][1] * c1 + G[0][2] * c2 - G[0][3] * c3;
    float vol = __fsqrt_rn(fmaxf(__fdiv_rn(det, 576.0f), 0.0f));

    // --- Seed (reference op order) ---
    float s1 = sigmoid_pos(__fmul_rn(vol, 10.0f));
    float s2 = sigmoid_pos(ratio);
    float s3 = sigmoid_pos(spread);
    float seed = __fadd_rn(__fadd_rn(__fmul_rn(s1, 0.4f), __fmul_rn(s2, 0.3f)),
                           __fmul_rn(s3, 0.3f));

    float x = fminf(fmaxf(seed, 1e-6f), 0.999999f);

    // --- Ternary Cantor digits ---
    float cantor = 0.0f;
    float factor = 0.5f;
#pragma unroll
    for (int it = 0; it < 8; ++it) {
        float xs = __fmul_rn(x, 3.0f);
        int d = (int)xs;
        x = __fsub_rn(xs, (float)d);
        if (d == 2) cantor = __fadd_rn(cantor, factor);
        factor *= 0.5f;
    }

    if (s == 0) out[g] = fminf(fmaxf(cantor, 0.0f), 1.0f);
}

extern "C" void kernel_launch(void* const* d_in, const int* in_sizes, int n_in,
                              void* d_out, int out_size)
{
    const float* p = (const float*)d_in[0];
    float* out = (float*)d_out;
    int V = in_sizes[0] / 640;                 // [V, 5, 128]
    long long total = (long long)V * 4;        // 4 lanes per pentachoron
    int threads = 256;
    int blocks = (int)((total + threads - 1) / threads);
    gpf_kernel<<<blocks, threads>>>(p, out, V);
}